// round 5
// baseline (speedup 1.0000x reference)
#include <cuda_runtime.h>
#include <cuda_bf16.h>
#include <math.h>

// Problem shape (fixed by the dataset): input [N, T] fp32, label [N] fp32.
static constexpr int N_ROWS = 8192;
static constexpr int T_COLS = 8192;

static constexpr int THREADS = 256;                 // per block
static constexpr int VECS_PER_THREAD = T_COLS / (THREADS * 4);  // 8 float4 each

// Global scratch: double accumulator for the final mean (no cudaMalloc allowed).
__device__ double g_loss_acc;

__global__ void init_acc_kernel() {
    g_loss_acc = 0.0;
}

__global__ __launch_bounds__(THREADS, 4)
void row_loss_kernel(const float* __restrict__ in,
                     const float* __restrict__ label) {
    const int row = blockIdx.x;
    const int tid = threadIdx.x;
    const size_t row_off = (size_t)row * T_COLS;
    const float4* rp = reinterpret_cast<const float4*>(in + row_off);

    // ---- Stage the whole row slice into registers (coalesced float4) ----
    float4 v[VECS_PER_THREAD];
#pragma unroll
    for (int k = 0; k < VECS_PER_THREAD; k++) {
        v[k] = rp[tid + k * THREADS];
    }

    // ---- Thread-local max ----
    float m = -INFINITY;
#pragma unroll
    for (int k = 0; k < VECS_PER_THREAD; k++) {
        m = fmaxf(m, fmaxf(fmaxf(v[k].x, v[k].y), fmaxf(v[k].z, v[k].w)));
    }

    // ---- Block reduce max ----
    __shared__ float s_red[THREADS / 32];
    __shared__ float s_max;
    __shared__ float s_sum;

#pragma unroll
    for (int off = 16; off > 0; off >>= 1)
        m = fmaxf(m, __shfl_xor_sync(0xFFFFFFFFu, m, off));
    if ((tid & 31) == 0) s_red[tid >> 5] = m;
    __syncthreads();
    if (tid < 32) {
        float mm = (tid < THREADS / 32) ? s_red[tid] : -INFINITY;
#pragma unroll
        for (int off = 4; off > 0; off >>= 1)
            mm = fmaxf(mm, __shfl_xor_sync(0xFFFFFFFFu, mm, off));
        if (tid == 0) s_max = mm;
    }
    __syncthreads();
    const float M = s_max;

    // ---- Sum of exp(x - M) : one MUFU per element ----
    float s = 0.0f;
#pragma unroll
    for (int k = 0; k < VECS_PER_THREAD; k++) {
        s += __expf(v[k].x - M);
        s += __expf(v[k].y - M);
        s += __expf(v[k].z - M);
        s += __expf(v[k].w - M);
    }
#pragma unroll
    for (int off = 16; off > 0; off >>= 1)
        s += __shfl_xor_sync(0xFFFFFFFFu, s, off);
    if ((tid & 31) == 0) s_red[tid >> 5] = s;
    __syncthreads();
    if (tid < 32) {
        float ss = (tid < THREADS / 32) ? s_red[tid] : 0.0f;
#pragma unroll
        for (int off = 4; off > 0; off >>= 1)
            ss += __shfl_xor_sync(0xFFFFFFFFu, ss, off);
        if (tid == 0) s_sum = ss;
    }
    __syncthreads();

    // ---- Thread 0: sparse target dot + row loss ----
    if (tid == 0) {
        const float lse = M + __logf(s_sum);

        const float lab = label[row];
        const float pos = lab * (float)T_COLS - 1.0f;
        const int fl = (int)floorf(pos);
        const int ce = (int)ceilf(pos);

        // Replicate reference write ORDER (later writes overwrite earlier).
        int   cols[4];
        float vals[4];
        cols[0] = max(fl - 1, 0);          vals[0] = 0.1f;
        cols[1] = fl;                      vals[1] = (fl >= 1) ? 0.4f : 0.5f;
        cols[2] = min(ce + 1, T_COLS - 1); vals[2] = 0.1f;
        cols[3] = ce;                      vals[3] = (ce < T_COLS - 1) ? 0.4f : 0.5f;

        float wsum = 0.0f, dot = 0.0f;
#pragma unroll
        for (int i = 0; i < 4; i++) {
            bool alive = true;
#pragma unroll
            for (int j = i + 1; j < 4; j++)
                if (cols[j] == cols[i]) alive = false;   // last write wins
            if (alive) {
                const float x = in[row_off + cols[i]];   // L1-hot: row just streamed
                wsum += vals[i];
                dot  += vals[i] * x;
            }
        }

        const float row_loss = wsum * lse - dot;
        atomicAdd(&g_loss_acc, (double)row_loss);
    }
}

__global__ void finalize_kernel(float* __restrict__ out) {
    out[0] = (float)(g_loss_acc / (double)N_ROWS);
}

extern "C" void kernel_launch(void* const* d_in, const int* in_sizes, int n_in,
                              void* d_out, int out_size) {
    const float* input = (const float*)d_in[0];   // [N, T] fp32
    const float* label = (const float*)d_in[1];   // [N] fp32
    float* out = (float*)d_out;

    init_acc_kernel<<<1, 1>>>();
    row_loss_kernel<<<N_ROWS, THREADS>>>(input, label);
    finalize_kernel<<<1, 1>>>(out);
}